// round 9
// baseline (speedup 1.0000x reference)
#include <cuda_runtime.h>
#include <cuda_fp16.h>
#include <cstdint>

// LDDMM variational shooting RHS via mma.sync (HMMA, family-level PTX).
//   e_ij = exp(-50*|xi-xj|^2)  (fp32 ALU, exp2 expansion form)
//   All j-reductions as one MMA stream D = E @ B, B[24 cols]:
//     col t<3 : hi(pj_t)      t in [3,6): lo(pj_{t-3})
//     t in [6,15):  hi(pj_c*xj_d), c=(t-6)/3, d=(t-6)%3
//     t in [15,24): lo(pj_c*xj_d)
//   Epilogue: dcp_c = D[c]+D[c+3];  M_cd = D[6+3c+d]+D[15+3c+d]
//             sw = pi.dcp;  dmom_d = 100*(xi_d*sw - sum_c pi_c*M_cd)
// Output layout: [dmom (N*3) | dcp (N*3)].

#define TPB      256
#define JSPLIT   8
#define ITILE    128
#define CHUNK    256
#define BS_STRIDE 264   // halves; 8-way-conflict-free fragment loads

typedef unsigned long long u64;

#define CE   (-72.13475204444817f)   // -50 * log2(e)
#define CEM2 (144.26950408889634f)   // -2 * CE

__device__ __forceinline__ u64 f2pack(float lo, float hi) {
    u64 r; asm("mov.b64 %0, {%1, %2};" : "=l"(r) : "f"(lo), "f"(hi)); return r;
}
__device__ __forceinline__ void f2unpack(u64 v, float& lo, float& hi) {
    asm("mov.b64 {%0, %1}, %2;" : "=f"(lo), "=f"(hi) : "l"(v));
}
__device__ __forceinline__ u64 fma2(u64 a, u64 b, u64 c) {
    u64 d; asm("fma.rn.f32x2 %0, %1, %2, %3;" : "=l"(d) : "l"(a), "l"(b), "l"(c)); return d;
}
__device__ __forceinline__ u64 add2(u64 a, u64 b) {
    u64 d; asm("add.rn.f32x2 %0, %1, %2;" : "=l"(d) : "l"(a), "l"(b)); return d;
}
__device__ __forceinline__ float ex2(float x) {
    float r; asm("ex2.approx.f32 %0, %1;" : "=f"(r) : "f"(x)); return r;
}
// pack (lo -> low half, hi -> high half); first PTX source lands in HIGH half.
__device__ __forceinline__ uint32_t cvt_f16x2(float lo, float hi) {
    uint32_t r; asm("cvt.rn.f16x2.f32 %0, %1, %2;" : "=r"(r) : "f"(hi), "f"(lo)); return r;
}
__device__ __forceinline__ float clamp1(float v) { return fminf(1.0f, fmaxf(-1.0f, v)); }

__device__ __forceinline__ void mma16816(float* d, uint32_t a0, uint32_t a1,
                                         uint32_t a2, uint32_t a3,
                                         uint32_t b0, uint32_t b1) {
    asm volatile(
        "mma.sync.aligned.m16n8k16.row.col.f32.f16.f16.f32 "
        "{%0,%1,%2,%3}, {%4,%5,%6,%7}, {%8,%9}, {%0,%1,%2,%3};"
        : "+f"(d[0]), "+f"(d[1]), "+f"(d[2]), "+f"(d[3])
        : "r"(a0), "r"(a1), "r"(a2), "r"(a3), "r"(b0), "r"(b1));
}

__global__ void zero_out_kernel(float* __restrict__ out, int n) {
    int i = blockIdx.x * blockDim.x + threadIdx.x;
    if (i < n) out[i] = 0.0f;
}

__global__ __launch_bounds__(TPB)
void lddmm_hmma_kernel(const float* __restrict__ mom,
                       const float* __restrict__ x,
                       float* __restrict__ out,
                       int N)
{
    __shared__ __align__(16) float sx0[CHUNK], sx1[CHUNK], sx2[CHUNK], scj[CHUNK];
    // union: Bs (24 x BS_STRIDE halves = 12672B) / Ds (128 x 24 floats = 12288B)
    __shared__ __align__(16) char ubuf[24 * BS_STRIDE * 2];
    __half* Bs = (__half*)ubuf;
    float*  Ds = (float*)ubuf;

    const int tid  = threadIdx.x;
    const int warp = tid >> 5;
    const int lane = tid & 31;

    const int i0  = blockIdx.x * ITILE;
    const int rA  = warp * 16 + (lane >> 2);   // local row for a0/a2
    const int rB  = rA + 8;                    // local row for a1/a3
    const int iA  = i0 + rA;
    const int iB  = i0 + rB;

    // per-row packed constants
    u64 A_[2], X0_[2], X1_[2], X2_[2];
    {
        const int ir[2] = { iA, iB };
        #pragma unroll
        for (int r = 0; r < 2; r++) {
            const float a = x[3 * ir[r] + 0], b = x[3 * ir[r] + 1], c = x[3 * ir[r] + 2];
            const float av = CE * (a * a + b * b + c * c);
            A_[r]  = f2pack(av, av);
            X0_[r] = f2pack(CEM2 * a, CEM2 * a);
            X1_[r] = f2pack(CEM2 * b, CEM2 * b);
            X2_[r] = f2pack(CEM2 * c, CEM2 * c);
        }
    }

    float D[3][4];
    #pragma unroll
    for (int g = 0; g < 3; g++)
        #pragma unroll
        for (int q = 0; q < 4; q++) D[g][q] = 0.0f;

    const int jrange = N / JSPLIT;           // 1024
    const int chunks = jrange / CHUNK;       // 4
    const int jbase  = blockIdx.y * jrange;

    const int k0 = (lane & 3) << 1;          // j-pair offset within 16-subtile
    const int tcol = lane >> 2;              // B col within 8-group

    for (int ch = 0; ch < chunks; ch++) {
        __syncthreads();   // previous subtile reads done before overwrite

        // ---- build SoA + B (thread tid handles j = tid) ----
        {
            const int g = jbase + ch * CHUNK + tid;
            const float a = x[3 * g + 0], b = x[3 * g + 1], c = x[3 * g + 2];
            sx0[tid] = a; sx1[tid] = b; sx2[tid] = c;
            scj[tid] = CE * (a * a + b * b + c * c);
            const float pv[3] = { clamp1(mom[3 * g + 0]),
                                  clamp1(mom[3 * g + 1]),
                                  clamp1(mom[3 * g + 2]) };
            const float xv[3] = { a, b, c };
            #pragma unroll
            for (int c2 = 0; c2 < 3; c2++) {
                const __half hi = __float2half_rn(pv[c2]);
                const __half lo = __float2half_rn(pv[c2] - __half2float(hi));
                Bs[c2 * BS_STRIDE + tid]       = hi;
                Bs[(c2 + 3) * BS_STRIDE + tid] = lo;
            }
            #pragma unroll
            for (int c2 = 0; c2 < 3; c2++)
                #pragma unroll
                for (int d2 = 0; d2 < 3; d2++) {
                    const float q = pv[c2] * xv[d2];
                    const __half hi = __float2half_rn(q);
                    const __half lo = __float2half_rn(q - __half2float(hi));
                    Bs[(6 + 3 * c2 + d2) * BS_STRIDE + tid]  = hi;
                    Bs[(15 + 3 * c2 + d2) * BS_STRIDE + tid] = lo;
                }
        }
        __syncthreads();

        // ---- 16 j-subtiles of 16 ----
        #pragma unroll 2
        for (int st = 0; st < CHUNK / 16; st++) {
            const int ja = st * 16 + k0;      // first j-pair
            const int jb = ja + 8;            // second j-pair

            const u64 x0a = *(const u64*)&sx0[ja];
            const u64 x1a = *(const u64*)&sx1[ja];
            const u64 x2a = *(const u64*)&sx2[ja];
            const u64 cja = *(const u64*)&scj[ja];
            const u64 x0b = *(const u64*)&sx0[jb];
            const u64 x1b = *(const u64*)&sx1[jb];
            const u64 x2b = *(const u64*)&sx2[jb];
            const u64 cjb = *(const u64*)&scj[jb];

            uint32_t ea[4];
            #pragma unroll
            for (int r = 0; r < 2; r++) {
                u64 t = add2(A_[r], cja);
                t = fma2(X0_[r], x0a, t);
                t = fma2(X1_[r], x1a, t);
                t = fma2(X2_[r], x2a, t);
                float tl, th; f2unpack(t, tl, th);
                ea[r] = cvt_f16x2(ex2(tl), ex2(th));      // a0 (r=0), a1 (r=1)

                u64 s = add2(A_[r], cjb);
                s = fma2(X0_[r], x0b, s);
                s = fma2(X1_[r], x1b, s);
                s = fma2(X2_[r], x2b, s);
                float sl, sh; f2unpack(s, sl, sh);
                ea[2 + r] = cvt_f16x2(ex2(sl), ex2(sh));  // a2 (r=0), a3 (r=1)
            }

            #pragma unroll
            for (int g = 0; g < 3; g++) {
                const int t = 8 * g + tcol;
                const uint32_t b0 = *(const uint32_t*)&Bs[t * BS_STRIDE + ja];
                const uint32_t b1 = *(const uint32_t*)&Bs[t * BS_STRIDE + jb];
                mma16816(D[g], ea[0], ea[1], ea[2], ea[3], b0, b1);
            }
        }
    }

    // ---- epilogue: stage D fragments, then one thread per i ----
    __syncthreads();   // done with Bs; ubuf becomes Ds
    #pragma unroll
    for (int g = 0; g < 3; g++) {
        const int cc = 8 * g + k0;
        Ds[rA * 24 + cc + 0] = D[g][0];
        Ds[rA * 24 + cc + 1] = D[g][1];
        Ds[rB * 24 + cc + 0] = D[g][2];
        Ds[rB * 24 + cc + 1] = D[g][3];
    }
    __syncthreads();

    if (tid < ITILE) {
        const int i = i0 + tid;
        const float* Drow = &Ds[tid * 24];
        const float pi0 = clamp1(mom[3 * i + 0]);
        const float pi1 = clamp1(mom[3 * i + 1]);
        const float pi2 = clamp1(mom[3 * i + 2]);
        const float xi[3] = { x[3 * i + 0], x[3 * i + 1], x[3 * i + 2] };
        const float pi[3] = { pi0, pi1, pi2 };

        const float dcp0 = Drow[0] + Drow[3];
        const float dcp1 = Drow[1] + Drow[4];
        const float dcp2 = Drow[2] + Drow[5];
        const float sw = pi0 * dcp0 + pi1 * dcp1 + pi2 * dcp2;

        float* dcp = out + 3 * N;
        #pragma unroll
        for (int d = 0; d < 3; d++) {
            float sx = 0.0f;
            #pragma unroll
            for (int c = 0; c < 3; c++)
                sx += pi[c] * (Drow[6 + 3 * c + d] + Drow[15 + 3 * c + d]);
            atomicAdd(&out[3 * i + d], 100.0f * (xi[d] * sw - sx));
        }
        atomicAdd(&dcp[3 * i + 0], dcp0);
        atomicAdd(&dcp[3 * i + 1], dcp1);
        atomicAdd(&dcp[3 * i + 2], dcp2);
    }
}

extern "C" void kernel_launch(void* const* d_in, const int* in_sizes, int n_in,
                              void* d_out, int out_size) {
    const float* mom = (const float*)d_in[0];
    const float* x   = (const float*)d_in[1];
    float* out = (float*)d_out;
    const int N = in_sizes[0] / 3;

    zero_out_kernel<<<(out_size + 255) / 256, 256>>>(out, out_size);

    dim3 grid(N / ITILE, JSPLIT);
    lddmm_hmma_kernel<<<grid, TPB>>>(mom, x, out, N);
}

// round 10
// speedup vs baseline: 1.8828x; 1.8828x over previous
#include <cuda_runtime.h>
#include <cuda_fp16.h>
#include <cstdint>

// LDDMM RHS, both stages on HMMA (family-level mma.sync).
// Stage 1:  T[16i x 16j] = A1 @ B1  (13-feature hi/lo-split f16 bilinear form)
//           t_ij = Ai + cj + sum_d (CEM2*xi_d)*xj_d = CE*|xi-xj|^2
// Register: e = ex2(t)  (1 MUFU per pair), cvt to f16x2 in A-fragment layout
//           (stage-1 D fragment slots == stage-2 A fragment slots).
// Stage 2:  D += E @ B2, B2[24 cols] = {hi/lo(pj_c), hi/lo(pj_c*xj_d)}
// Epilogue: dcp_c = D[c]+D[c+3]; M_cd = D[6+3c+d]+D[15+3c+d]
//           sw = pi.dcp; dmom_d = 100*(xi_d*sw - sum_c pi_c*M_cd)
// Output layout: [dmom (N*3) | dcp (N*3)].

#define TPB       256
#define JSPLIT    8
#define ITILE     128
#define CHUNK     256
#define BS_STRIDE 264    // halves; conflict-free stage-2 fragment loads

typedef unsigned long long u64;

#define CE   (-72.13475204444817f)   // -50 * log2(e)
#define CEM2 (144.26950408889634f)   // -2 * CE

__device__ __forceinline__ float ex2(float x) {
    float r; asm("ex2.approx.f32 %0, %1;" : "=f"(r) : "f"(x)); return r;
}
// pack (lo -> low half, hi -> high half); first PTX source lands in HIGH half.
__device__ __forceinline__ uint32_t cvt_f16x2(float lo, float hi) {
    uint32_t r; asm("cvt.rn.f16x2.f32 %0, %1, %2;" : "=r"(r) : "f"(hi), "f"(lo)); return r;
}
__device__ __forceinline__ float clamp1(float v) { return fminf(1.0f, fmaxf(-1.0f, v)); }

// accumulate: D += A@B
__device__ __forceinline__ void mma16816(float* d, uint32_t a0, uint32_t a1,
                                         uint32_t a2, uint32_t a3,
                                         uint32_t b0, uint32_t b1) {
    asm volatile(
        "mma.sync.aligned.m16n8k16.row.col.f32.f16.f16.f32 "
        "{%0,%1,%2,%3}, {%4,%5,%6,%7}, {%8,%9}, {%0,%1,%2,%3};"
        : "+f"(d[0]), "+f"(d[1]), "+f"(d[2]), "+f"(d[3])
        : "r"(a0), "r"(a1), "r"(a2), "r"(a3), "r"(b0), "r"(b1));
}
// zero-C: D = A@B
__device__ __forceinline__ void mma16816_c0(float* d, uint32_t a0, uint32_t a1,
                                            uint32_t a2, uint32_t a3,
                                            uint32_t b0, uint32_t b1) {
    asm volatile(
        "mma.sync.aligned.m16n8k16.row.col.f32.f16.f16.f32 "
        "{%0,%1,%2,%3}, {%4,%5,%6,%7}, {%8,%9}, {%10,%10,%10,%10};"
        : "=f"(d[0]), "=f"(d[1]), "=f"(d[2]), "=f"(d[3])
        : "r"(a0), "r"(a1), "r"(a2), "r"(a3), "r"(b0), "r"(b1), "f"(0.0f));
}

__device__ __forceinline__ void hl_split(float v, __half& h, __half& l) {
    h = __float2half_rn(v);
    l = __float2half_rn(v - __half2float(h));
}

__global__ void zero_out_kernel(float* __restrict__ out, int n) {
    int i = blockIdx.x * blockDim.x + threadIdx.x;
    if (i < n) out[i] = 0.0f;
}

__global__ __launch_bounds__(TPB)
void lddmm_hmma2_kernel(const float* __restrict__ mom,
                        const float* __restrict__ x,
                        float* __restrict__ out,
                        int N)
{
    // Stage-1 A features (row-major, 16 halves/row), built once.
    __shared__ __align__(16) __half As[ITILE * 16];            // 4 KB
    // Stage-1 B features per chunk: k0..7 in B1L, k8..15 in B1H (col stride 8 halves).
    __shared__ __align__(16) __half B1L[CHUNK * 8];            // 4 KB
    __shared__ __align__(16) __half B1H[CHUNK * 8];            // 4 KB
    // Stage-2 B (24 x BS_STRIDE halves) / epilogue D staging (128 x 24 f32).
    __shared__ __align__(16) char ubuf[24 * BS_STRIDE * 2];    // 12.4 KB
    __half* Bs = (__half*)ubuf;
    float*  Ds = (float*)ubuf;

    const int tid  = threadIdx.x;
    const int warp = tid >> 5;
    const int lane = tid & 31;

    const int i0  = blockIdx.x * ITILE;
    const int rA  = warp * 16 + (lane >> 2);
    const int rB  = rA + 8;
    const int kf0 = (lane & 3) << 1;
    const int tcol = lane >> 2;

    // ---- build stage-1 A features (once) ----
    if (tid < ITILE) {
        const int i = i0 + tid;
        const float a = x[3 * i + 0], b = x[3 * i + 1], c = x[3 * i + 2];
        const float Ai = CE * (a * a + b * b + c * c);
        __half h, l;
        __half* R = &As[tid * 16];
        hl_split(a, h, l);
        R[0] = h; R[1] = h; R[2] = __float2half_rn(__half2float(l) * 2048.0f);
        hl_split(b, h, l);
        R[3] = h; R[4] = h; R[5] = __float2half_rn(__half2float(l) * 2048.0f);
        hl_split(c, h, l);
        R[6] = h; R[7] = h; R[8] = __float2half_rn(__half2float(l) * 2048.0f);
        hl_split(Ai, h, l);
        R[9] = h; R[10] = l;
        R[11] = __float2half_rn(1.0f); R[12] = __float2half_rn(1.0f);
        R[13] = __ushort_as_half(0); R[14] = __ushort_as_half(0); R[15] = __ushort_as_half(0);
    }
    __syncthreads();

    // Stage-1 A fragment: constant for the whole kernel (4 regs).
    const uint32_t A10 = *(const uint32_t*)&As[rA * 16 + kf0];
    const uint32_t A11 = *(const uint32_t*)&As[rB * 16 + kf0];
    const uint32_t A12 = *(const uint32_t*)&As[rA * 16 + kf0 + 8];
    const uint32_t A13 = *(const uint32_t*)&As[rB * 16 + kf0 + 8];

    float D[3][4];
    #pragma unroll
    for (int g = 0; g < 3; g++)
        #pragma unroll
        for (int q = 0; q < 4; q++) D[g][q] = 0.0f;

    const int jrange = N / JSPLIT;
    const int chunks = jrange / CHUNK;
    const int jbase  = blockIdx.y * jrange;

    for (int ch = 0; ch < chunks; ch++) {
        __syncthreads();   // prior subtile reads finished

        // ---- build stage-1 B + stage-2 B: thread tid owns column j = tid ----
        {
            const int g = jbase + ch * CHUNK + tid;
            const float a = x[3 * g + 0], b = x[3 * g + 1], c = x[3 * g + 2];
            const float cj = CE * (a * a + b * b + c * c);
            __half h, l;
            __half* L = &B1L[tid * 8];
            __half* H = &B1H[tid * 8];
            hl_split(CEM2 * a, h, l);
            L[0] = h; L[1] = l; L[2] = __float2half_rn(__half2float(h) * (1.0f / 2048.0f));
            hl_split(CEM2 * b, h, l);
            L[3] = h; L[4] = l; L[5] = __float2half_rn(__half2float(h) * (1.0f / 2048.0f));
            hl_split(CEM2 * c, h, l);
            L[6] = h; L[7] = l;
            H[0] = __float2half_rn(__half2float(h) * (1.0f / 2048.0f));
            H[1] = __float2half_rn(1.0f); H[2] = __float2half_rn(1.0f);
            hl_split(cj, h, l);
            H[3] = h; H[4] = l;
            H[5] = __ushort_as_half(0); H[6] = __ushort_as_half(0); H[7] = __ushort_as_half(0);

            const float pv[3] = { clamp1(mom[3 * g + 0]),
                                  clamp1(mom[3 * g + 1]),
                                  clamp1(mom[3 * g + 2]) };
            const float xv[3] = { a, b, c };
            #pragma unroll
            for (int c2 = 0; c2 < 3; c2++) {
                hl_split(pv[c2], h, l);
                Bs[c2 * BS_STRIDE + tid]       = h;
                Bs[(c2 + 3) * BS_STRIDE + tid] = l;
            }
            #pragma unroll
            for (int c2 = 0; c2 < 3; c2++)
                #pragma unroll
                for (int d2 = 0; d2 < 3; d2++) {
                    hl_split(pv[c2] * xv[d2], h, l);
                    Bs[(6 + 3 * c2 + d2) * BS_STRIDE + tid]  = h;
                    Bs[(15 + 3 * c2 + d2) * BS_STRIDE + tid] = l;
                }
        }
        __syncthreads();

        // ---- 16 j-subtiles of 16 ----
        #pragma unroll 2
        for (int st = 0; st < CHUNK / 16; st++) {
            const int cb = st * 16;

            // Stage 1: two n-blocks of 8 j's -> T fragments (fp32).
            const int c0 = cb + tcol;
            const uint32_t b0 = *(const uint32_t*)&B1L[c0 * 8 + kf0];
            const uint32_t b1 = *(const uint32_t*)&B1H[c0 * 8 + kf0];
            float t0[4];
            mma16816_c0(t0, A10, A11, A12, A13, b0, b1);

            const int c1 = c0 + 8;
            const uint32_t b2 = *(const uint32_t*)&B1L[c1 * 8 + kf0];
            const uint32_t b3 = *(const uint32_t*)&B1H[c1 * 8 + kf0];
            float t1[4];
            mma16816_c0(t1, A10, A11, A12, A13, b2, b3);

            // e = 2^t, straight into stage-2 A-fragment registers.
            const uint32_t ea0 = cvt_f16x2(ex2(t0[0]), ex2(t0[1]));
            const uint32_t ea1 = cvt_f16x2(ex2(t0[2]), ex2(t0[3]));
            const uint32_t ea2 = cvt_f16x2(ex2(t1[0]), ex2(t1[1]));
            const uint32_t ea3 = cvt_f16x2(ex2(t1[2]), ex2(t1[3]));

            // Stage 2: 3 MMAs into persistent D.
            const int ja = cb + kf0;
            const int jb = ja + 8;
            #pragma unroll
            for (int g = 0; g < 3; g++) {
                const int t = 8 * g + tcol;
                const uint32_t s0 = *(const uint32_t*)&Bs[t * BS_STRIDE + ja];
                const uint32_t s1 = *(const uint32_t*)&Bs[t * BS_STRIDE + jb];
                mma16816(D[g], ea0, ea1, ea2, ea3, s0, s1);
            }
        }
    }

    // ---- epilogue: stage D fragments, one thread per i ----
    __syncthreads();   // done with Bs; ubuf becomes Ds
    #pragma unroll
    for (int g = 0; g < 3; g++) {
        const int cc = 8 * g + kf0;
        Ds[rA * 24 + cc + 0] = D[g][0];
        Ds[rA * 24 + cc + 1] = D[g][1];
        Ds[rB * 24 + cc + 0] = D[g][2];
        Ds[rB * 24 + cc + 1] = D[g][3];
    }
    __syncthreads();

    if (tid < ITILE) {
        const int i = i0 + tid;
        const float* Drow = &Ds[tid * 24];
        const float pi0 = clamp1(mom[3 * i + 0]);
        const float pi1 = clamp1(mom[3 * i + 1]);
        const float pi2 = clamp1(mom[3 * i + 2]);
        const float xi[3] = { x[3 * i + 0], x[3 * i + 1], x[3 * i + 2] };
        const float pi[3] = { pi0, pi1, pi2 };

        const float dcp0 = Drow[0] + Drow[3];
        const float dcp1 = Drow[1] + Drow[4];
        const float dcp2 = Drow[2] + Drow[5];
        const float sw = pi0 * dcp0 + pi1 * dcp1 + pi2 * dcp2;

        float* dcp = out + 3 * N;
        #pragma unroll
        for (int d = 0; d < 3; d++) {
            float sx = 0.0f;
            #pragma unroll
            for (int c = 0; c < 3; c++)
                sx += pi[c] * (Drow[6 + 3 * c + d] + Drow[15 + 3 * c + d]);
            atomicAdd(&out[3 * i + d], 100.0f * (xi[d] * sw - sx));
        }
        atomicAdd(&dcp[3 * i + 0], dcp0);
        atomicAdd(&dcp[3 * i + 1], dcp1);
        atomicAdd(&dcp[3 * i + 2], dcp2);
    }
}

extern "C" void kernel_launch(void* const* d_in, const int* in_sizes, int n_in,
                              void* d_out, int out_size) {
    const float* mom = (const float*)d_in[0];
    const float* x   = (const float*)d_in[1];
    float* out = (float*)d_out;
    const int N = in_sizes[0] / 3;

    zero_out_kernel<<<(out_size + 255) / 256, 256>>>(out, out_size);

    dim3 grid(N / ITILE, JSPLIT);
    lddmm_hmma2_kernel<<<grid, TPB>>>(mom, x, out, N);
}

// round 11
// speedup vs baseline: 2.1179x; 1.1249x over previous
#include <cuda_runtime.h>
#include <cuda_fp16.h>
#include <cstdint>

// LDDMM RHS, both stages on HMMA (family-level mma.sync).
// Stage 1:  T = A1@B1 (13-feature hi/lo f16 bilinear form) = CE*|xi-xj|^2
// Register: e = ex2.approx.f16x2(t)  -> directly stage-2 A fragments
// Stage 2:  D += E @ B2[24] = {hi/lo(pj_c), hi/lo(pj_c*xj_d)}
// Epilogue: dcp_c = D[c]+D[c+3]; M_cd = D[6+3c+d]+D[15+3c+d]
//           sw = pi.dcp; dmom_d = 100*(xi_d*sw - sum_c pi_c*M_cd)
// Output layout: [dmom (N*3) | dcp (N*3)].
// k-pair-interleaved SMEM layouts -> all fragment loads are LDS.64;
// subtile loop fully unrolled -> immediate-offset addressing.

#define TPB       256
#define JSPLIT    16
#define ITILE     128
#define CHUNK     256
#define BS_STRIDE 264    // halves per stage-2 row

typedef unsigned long long u64;

#define CE   (-72.13475204444817f)   // -50 * log2(e)
#define CEM2 (144.26950408889634f)   // -2 * CE

// pack (lo -> low half, hi -> high half); first PTX source lands in HIGH half.
__device__ __forceinline__ uint32_t cvt_f16x2(float lo, float hi) {
    uint32_t r; asm("cvt.rn.f16x2.f32 %0, %1, %2;" : "=r"(r) : "f"(hi), "f"(lo)); return r;
}
__device__ __forceinline__ uint32_t ex2_f16x2(uint32_t v) {
    uint32_t r; asm("ex2.approx.f16x2 %0, %1;" : "=r"(r) : "r"(v)); return r;
}
__device__ __forceinline__ float clamp1(float v) { return fminf(1.0f, fmaxf(-1.0f, v)); }

__device__ __forceinline__ void mma16816(float* d, uint32_t a0, uint32_t a1,
                                         uint32_t a2, uint32_t a3,
                                         uint32_t b0, uint32_t b1) {
    asm volatile(
        "mma.sync.aligned.m16n8k16.row.col.f32.f16.f16.f32 "
        "{%0,%1,%2,%3}, {%4,%5,%6,%7}, {%8,%9}, {%0,%1,%2,%3};"
        : "+f"(d[0]), "+f"(d[1]), "+f"(d[2]), "+f"(d[3])
        : "r"(a0), "r"(a1), "r"(a2), "r"(a3), "r"(b0), "r"(b1));
}
__device__ __forceinline__ void mma16816_c0(float* d, uint32_t a0, uint32_t a1,
                                            uint32_t a2, uint32_t a3,
                                            uint32_t b0, uint32_t b1) {
    asm volatile(
        "mma.sync.aligned.m16n8k16.row.col.f32.f16.f16.f32 "
        "{%0,%1,%2,%3}, {%4,%5,%6,%7}, {%8,%9}, {%10,%10,%10,%10};"
        : "=f"(d[0]), "=f"(d[1]), "=f"(d[2]), "=f"(d[3])
        : "r"(a0), "r"(a1), "r"(a2), "r"(a3), "r"(b0), "r"(b1), "f"(0.0f));
}

__device__ __forceinline__ void hl_split(float v, __half& h, __half& l) {
    h = __float2half_rn(v);
    l = __float2half_rn(v - __half2float(h));
}

__global__ void zero_out_kernel(float* __restrict__ out, int n) {
    int i = blockIdx.x * blockDim.x + threadIdx.x;
    if (i < n) out[i] = 0.0f;
}

__global__ __launch_bounds__(TPB)
void lddmm_hmma3_kernel(const float* __restrict__ mom,
                        const float* __restrict__ x,
                        float* __restrict__ out,
                        int N)
{
    // Stage-1 A features: row-major 16 halves/row (built once).
    __shared__ __align__(16) __half As[ITILE * 16];                 // 4 KB
    // Stage-1 B: per column 16 halves, k-pair interleaved [L0L1H0H1|L2L3H2H3|...].
    __shared__ __align__(16) __half B1[CHUNK * 16];                 // 8 KB
    // Stage-2 B (24 rows x BS_STRIDE halves, j-interleaved) / epilogue D staging.
    __shared__ __align__(16) char ubuf[24 * BS_STRIDE * 2];         // 12.4 KB
    __half* Bs = (__half*)ubuf;
    float*  Ds = (float*)ubuf;

    const int tid  = threadIdx.x;
    const int warp = tid >> 5;
    const int lane = tid & 31;

    const int i0   = blockIdx.x * ITILE;
    const int rA   = warp * 16 + (lane >> 2);
    const int rB   = rA + 8;
    const int kf0  = (lane & 3) << 1;      // k-pair base (0,2,4,6)
    const int tcol = lane >> 2;            // n-col within 8-group

    // ---- stage-1 A features (once) ----
    if (tid < ITILE) {
        const int i = i0 + tid;
        const float a = x[3 * i + 0], b = x[3 * i + 1], c = x[3 * i + 2];
        const float Ai = CE * (a * a + b * b + c * c);
        __half h, l;
        __half* R = &As[tid * 16];
        hl_split(a, h, l);
        R[0] = h; R[1] = h; R[2] = __float2half_rn(__half2float(l) * 2048.0f);
        hl_split(b, h, l);
        R[3] = h; R[4] = h; R[5] = __float2half_rn(__half2float(l) * 2048.0f);
        hl_split(c, h, l);
        R[6] = h; R[7] = h; R[8] = __float2half_rn(__half2float(l) * 2048.0f);
        hl_split(Ai, h, l);
        R[9] = h; R[10] = l;
        R[11] = __float2half_rn(1.0f); R[12] = __float2half_rn(1.0f);
        R[13] = __ushort_as_half(0); R[14] = __ushort_as_half(0); R[15] = __ushort_as_half(0);
    }
    __syncthreads();

    const uint32_t A10 = *(const uint32_t*)&As[rA * 16 + kf0];
    const uint32_t A11 = *(const uint32_t*)&As[rB * 16 + kf0];
    const uint32_t A12 = *(const uint32_t*)&As[rA * 16 + kf0 + 8];
    const uint32_t A13 = *(const uint32_t*)&As[rB * 16 + kf0 + 8];

    float D[3][4];
    #pragma unroll
    for (int g = 0; g < 3; g++)
        #pragma unroll
        for (int q = 0; q < 4; q++) D[g][q] = 0.0f;

    const int jrange = N / JSPLIT;           // 512
    const int chunks = jrange / CHUNK;       // 2
    const int jbase  = blockIdx.y * jrange;

    // Per-thread fragment base pointers (immediate offsets after unroll).
    const __half* b1base = &B1[tcol * 16 + (kf0 << 1)];
    const __half* b2base = &Bs[tcol * BS_STRIDE + (kf0 << 1)];

    for (int ch = 0; ch < chunks; ch++) {
        __syncthreads();

        // ---- build B1 (k-interleaved) + Bs (j-interleaved): thread owns j=tid ----
        {
            const int g = jbase + ch * CHUNK + tid;
            const float a = x[3 * g + 0], b = x[3 * g + 1], c = x[3 * g + 2];
            const float cj = CE * (a * a + b * b + c * c);
            __half h, l;
            // L_k at (k>>1)*4+(k&1); H_k at (k>>1)*4+2+(k&1)
            __half* C = &B1[tid * 16];
            hl_split(CEM2 * a, h, l);
            C[0] = h; C[1] = l;                       // L0, L1
            C[4] = __float2half_rn(__half2float(h) * (1.0f / 2048.0f));  // L2
            hl_split(CEM2 * b, h, l);
            C[5] = h; C[8] = l;                       // L3, L4
            C[9] = __float2half_rn(__half2float(h) * (1.0f / 2048.0f));  // L5
            hl_split(CEM2 * c, h, l);
            C[12] = h; C[13] = l;                     // L6, L7
            C[2] = __float2half_rn(__half2float(h) * (1.0f / 2048.0f));  // H0
            C[3] = __float2half_rn(1.0f);             // H1
            C[6] = __float2half_rn(1.0f);             // H2
            hl_split(cj, h, l);
            C[7] = h; C[10] = l;                      // H3, H4
            C[11] = __ushort_as_half(0); C[14] = __ushort_as_half(0);
            C[15] = __ushort_as_half(0);              // H5..H7

            // stage-2 column position: interleave (j, j+8) pairs inside 16-groups
            const int q = tid & 15;
            const int pos = (tid & ~15) + ((q & 6) >> 1) * 4 + (q & 1) + ((q & 8) >> 3) * 2;

            const float pv[3] = { clamp1(mom[3 * g + 0]),
                                  clamp1(mom[3 * g + 1]),
                                  clamp1(mom[3 * g + 2]) };
            const float xv[3] = { a, b, c };
            #pragma unroll
            for (int c2 = 0; c2 < 3; c2++) {
                hl_split(pv[c2], h, l);
                Bs[c2 * BS_STRIDE + pos]       = h;
                Bs[(c2 + 3) * BS_STRIDE + pos] = l;
            }
            #pragma unroll
            for (int c2 = 0; c2 < 3; c2++)
                #pragma unroll
                for (int d2 = 0; d2 < 3; d2++) {
                    hl_split(pv[c2] * xv[d2], h, l);
                    Bs[(6 + 3 * c2 + d2) * BS_STRIDE + pos]  = h;
                    Bs[(15 + 3 * c2 + d2) * BS_STRIDE + pos] = l;
                }
        }
        __syncthreads();

        // ---- 16 j-subtiles of 16, fully unrolled ----
        #pragma unroll
        for (int st = 0; st < CHUNK / 16; st++) {
            // Stage 1: one LDS.64 per 8-j n-block -> (b0,b1)
            const uint2 f0 = *(const uint2*)(b1base + st * 256);        // cols st*16+tcol
            const uint2 f1 = *(const uint2*)(b1base + st * 256 + 128);  // +8 cols
            float t0[4], t1[4];
            mma16816_c0(t0, A10, A11, A12, A13, f0.x, f0.y);
            mma16816_c0(t1, A10, A11, A12, A13, f1.x, f1.y);

            // e = 2^t in f16x2 (one MUFU per 2 pairs), straight to A fragments.
            const uint32_t ea0 = ex2_f16x2(cvt_f16x2(t0[0], t0[1]));
            const uint32_t ea1 = ex2_f16x2(cvt_f16x2(t0[2], t0[3]));
            const uint32_t ea2 = ex2_f16x2(cvt_f16x2(t1[0], t1[1]));
            const uint32_t ea3 = ex2_f16x2(cvt_f16x2(t1[2], t1[3]));

            // Stage 2: one LDS.64 per n-group -> (s0,s1); 3 MMAs into D.
            #pragma unroll
            for (int g = 0; g < 3; g++) {
                const uint2 s = *(const uint2*)(b2base + g * 8 * BS_STRIDE + st * 16);
                mma16816(D[g], ea0, ea1, ea2, ea3, s.x, s.y);
            }
        }
    }

    // ---- epilogue ----
    __syncthreads();   // done with Bs; ubuf becomes Ds
    #pragma unroll
    for (int g = 0; g < 3; g++) {
        const int cc = 8 * g + kf0;
        Ds[rA * 24 + cc + 0] = D[g][0];
        Ds[rA * 24 + cc + 1] = D[g][1];
        Ds[rB * 24 + cc + 0] = D[g][2];
        Ds[rB * 24 + cc + 1] = D[g][3];
    }
    __syncthreads();

    if (tid < ITILE) {
        const int i = i0 + tid;
        const float* Drow = &Ds[tid * 24];
        const float pi0 = clamp1(mom[3 * i + 0]);
        const float pi1 = clamp1(mom[3 * i + 1]);
        const float pi2 = clamp1(mom[3 * i + 2]);
        const float xi[3] = { x[3 * i + 0], x[3 * i + 1], x[3 * i + 2] };
        const float pi[3] = { pi0, pi1, pi2 };

        const float dcp0 = Drow[0] + Drow[3];
        const float dcp1 = Drow[1] + Drow[4];
        const float dcp2 = Drow[2] + Drow[5];
        const float sw = pi0 * dcp0 + pi1 * dcp1 + pi2 * dcp2;

        float* dcp = out + 3 * N;
        #pragma unroll
        for (int d = 0; d < 3; d++) {
            float sx = 0.0f;
            #pragma unroll
            for (int c = 0; c < 3; c++)
                sx += pi[c] * (Drow[6 + 3 * c + d] + Drow[15 + 3 * c + d]);
            atomicAdd(&out[3 * i + d], 100.0f * (xi[d] * sw - sx));
        }
        atomicAdd(&dcp[3 * i + 0], dcp0);
        atomicAdd(&dcp[3 * i + 1], dcp1);
        atomicAdd(&dcp[3 * i + 2], dcp2);
    }
}

extern "C" void kernel_launch(void* const* d_in, const int* in_sizes, int n_in,
                              void* d_out, int out_size) {
    const float* mom = (const float*)d_in[0];
    const float* x   = (const float*)d_in[1];
    float* out = (float*)d_out;
    const int N = in_sizes[0] / 3;

    zero_out_kernel<<<(out_size + 255) / 256, 256>>>(out, out_size);

    dim3 grid(N / ITILE, JSPLIT);
    lddmm_hmma3_kernel<<<grid, TPB>>>(mom, x, out, N);
}